// round 5
// baseline (speedup 1.0000x reference)
#include <cuda_runtime.h>
#include <math.h>

#define NN 50000
#define NE 800000
#define H 128
#define H3 384

// ---------------- device scratch (no allocs allowed) ----------------
__device__ float g_h0[NN * H];
__device__ float g_h1[NN * H];
__device__ float g_hw[NN * H];
__device__ float g_agg[NN * H];
__device__ float g_gcn[NN * H];
__device__ float g_gi[NN * H3];
__device__ float g_gh[NN * H3];
__device__ float g_deg[NN];
__device__ float g_dinv[NN];

// ---------------- SGEMM: C[M,Ncol] = act(A[M,K] @ B[K,Ncol] + bias) ----------------
// BM=BN=128, BK=8, 256 threads, 8x8 register tile.
__global__ void __launch_bounds__(256, 2) sgemm_k(
    const float* __restrict__ A, const float* __restrict__ B,
    const float* __restrict__ bias, float* __restrict__ C,
    int M, int Ncol, int K, int act)
{
    __shared__ float As[8][128];
    __shared__ float Bs[8][128];
    const int tid = threadIdx.x;
    const int bx = blockIdx.x, by = blockIdx.y;
    const int row0 = by * 128;
    const int col0 = bx * 128;
    const int aRow = tid >> 1;
    const int aCol = (tid & 1) << 2;
    const int bRow = tid >> 5;
    const int bCol = (tid & 31) << 2;
    const int tr = (tid >> 4) << 3;
    const int tc = (tid & 15) << 3;
    float acc[8][8] = {};

    for (int k0 = 0; k0 < K; k0 += 8) {
        float4 av = make_float4(0.f, 0.f, 0.f, 0.f);
        int gr = row0 + aRow;
        if (gr < M)
            av = *reinterpret_cast<const float4*>(&A[(size_t)gr * K + k0 + aCol]);
        As[aCol + 0][aRow] = av.x;
        As[aCol + 1][aRow] = av.y;
        As[aCol + 2][aRow] = av.z;
        As[aCol + 3][aRow] = av.w;
        *reinterpret_cast<float4*>(&Bs[bRow][bCol]) =
            *reinterpret_cast<const float4*>(&B[(size_t)(k0 + bRow) * Ncol + col0 + bCol]);
        __syncthreads();
#pragma unroll
        for (int k = 0; k < 8; k++) {
            float ar[8], br[8];
#pragma unroll
            for (int i = 0; i < 8; i++) ar[i] = As[k][tr + i];
#pragma unroll
            for (int j = 0; j < 8; j++) br[j] = Bs[k][tc + j];
#pragma unroll
            for (int i = 0; i < 8; i++)
#pragma unroll
                for (int j = 0; j < 8; j++)
                    acc[i][j] = fmaf(ar[i], br[j], acc[i][j]);
        }
        __syncthreads();
    }

#pragma unroll
    for (int i = 0; i < 8; i++) {
        int gr = row0 + tr + i;
        if (gr >= M) break;
#pragma unroll
        for (int j0 = 0; j0 < 8; j0 += 4) {
            float4 v;
            v.x = acc[i][j0]; v.y = acc[i][j0 + 1]; v.z = acc[i][j0 + 2]; v.w = acc[i][j0 + 3];
            if (bias) {
                const float4 bv = *reinterpret_cast<const float4*>(&bias[col0 + tc + j0]);
                v.x += bv.x; v.y += bv.y; v.z += bv.z; v.w += bv.w;
            }
            if (act) {
                v.x = v.x >= 0.f ? v.x : 0.01f * v.x;
                v.y = v.y >= 0.f ? v.y : 0.01f * v.y;
                v.z = v.z >= 0.f ? v.z : 0.01f * v.z;
                v.w = v.w >= 0.f ? v.w : 0.01f * v.w;
            }
            *reinterpret_cast<float4*>(&C[(size_t)gr * Ncol + col0 + tc + j0]) = v;
        }
    }
}

// ---------------- helpers ----------------
__global__ void zero_k(float* __restrict__ p, int n4)
{
    int i = blockIdx.x * blockDim.x + threadIdx.x;
    if (i < n4) reinterpret_cast<float4*>(p)[i] = make_float4(0.f, 0.f, 0.f, 0.f);
}

__global__ void deg_acc_k(const int* __restrict__ dst, float* __restrict__ deg)
{
    int i = blockIdx.x * blockDim.x + threadIdx.x;
    if (i < NE) {
        int d = dst[i];
        if (d >= 0 && d < NN) atomicAdd(&deg[d], 1.0f);
    }
}

__global__ void dinv_k(const float* __restrict__ deg, float* __restrict__ dinv)
{
    int i = blockIdx.x * blockDim.x + threadIdx.x;
    if (i < NN) dinv[i] = rsqrtf(deg[i] + 1.0f);
}

// one warp per edge: gather hw[src] row (128 floats = 32 lanes x float4),
// scale by dinv[src]*dinv[dst], scalar atomic reductions into agg[dst].
__global__ void scatter_k(const int* __restrict__ src, const int* __restrict__ dst,
                          const float* __restrict__ hw, const float* __restrict__ dinv,
                          float* __restrict__ agg)
{
    int gwarp = (blockIdx.x * blockDim.x + threadIdx.x) >> 5;
    int lane = threadIdx.x & 31;
    int nwarps = (gridDim.x * blockDim.x) >> 5;
    for (int e = gwarp; e < NE; e += nwarps) {
        int s = src[e];
        int d = dst[e];
        if ((unsigned)s >= NN || (unsigned)d >= NN) continue;
        float nrm = dinv[s] * dinv[d];
        float4 v = reinterpret_cast<const float4*>(&hw[(size_t)s * H])[lane];
        float* ap = &agg[(size_t)d * H + lane * 4];
        atomicAdd(ap + 0, v.x * nrm);
        atomicAdd(ap + 1, v.y * nrm);
        atomicAdd(ap + 2, v.z * nrm);
        atomicAdd(ap + 3, v.w * nrm);
    }
}

// out = lrelu(agg + hw * dinv^2 + bias)
__global__ void combine_k(const float* __restrict__ agg, const float* __restrict__ hw,
                          const float* __restrict__ dinv, const float* __restrict__ bias,
                          float* __restrict__ out)
{
    int i = blockIdx.x * blockDim.x + threadIdx.x;  // float4 index
    if (i >= NN * H / 4) return;
    int nrow = i / (H / 4);
    int c4 = i % (H / 4);
    float di = dinv[nrow];
    float d2 = di * di;
    float4 a = reinterpret_cast<const float4*>(agg)[i];
    float4 w = reinterpret_cast<const float4*>(hw)[i];
    float4 b = reinterpret_cast<const float4*>(bias)[c4];
    float4 r;
    r.x = a.x + w.x * d2 + b.x;
    r.y = a.y + w.y * d2 + b.y;
    r.z = a.z + w.z * d2 + b.z;
    r.w = a.w + w.w * d2 + b.w;
    r.x = r.x >= 0.f ? r.x : 0.01f * r.x;
    r.y = r.y >= 0.f ? r.y : 0.01f * r.y;
    r.z = r.z >= 0.f ? r.z : 0.01f * r.z;
    r.w = r.w >= 0.f ? r.w : 0.01f * r.w;
    reinterpret_cast<float4*>(out)[i] = r;
}

__device__ __forceinline__ float sigm(float x) { return 1.0f / (1.0f + expf(-x)); }

__global__ void gru_k(const float* __restrict__ gi, const float* __restrict__ gh,
                      const float* __restrict__ prev, float* __restrict__ out)
{
    int i = blockIdx.x * blockDim.x + threadIdx.x;
    if (i >= NN * H) return;
    int nrow = i / H;
    int c = i % H;
    size_t base = (size_t)nrow * H3 + c;
    float ir = gi[base], iz = gi[base + H], inn = gi[base + 2 * H];
    float hr = gh[base], hz = gh[base + H], hn = gh[base + 2 * H];
    float r = sigm(ir + hr);
    float z = sigm(iz + hz);
    float nn_ = tanhf(inn + r * hn);
    out[i] = (1.0f - z) * nn_ + z * prev[i];
}

// out[n] = dot(h[n,:], w) + b : one warp per node
__global__ void post_k(const float* __restrict__ h, const float* __restrict__ w,
                       const float* __restrict__ b, float* __restrict__ out)
{
    int gwarp = (blockIdx.x * blockDim.x + threadIdx.x) >> 5;
    int lane = threadIdx.x & 31;
    if (gwarp >= NN) return;
    float4 wv = reinterpret_cast<const float4*>(w)[lane];
    float4 hv = reinterpret_cast<const float4*>(&h[(size_t)gwarp * H])[lane];
    float s = hv.x * wv.x + hv.y * wv.y + hv.z * wv.z + hv.w * wv.w;
#pragma unroll
    for (int o = 16; o; o >>= 1) s += __shfl_xor_sync(0xFFFFFFFFu, s, o);
    if (lane == 0) out[gwarp] = s + b[0];
}

// ---------------- launch ----------------
extern "C" void kernel_launch(void* const* d_in, const int* in_sizes, int n_in,
                              void* d_out, int out_size)
{
    const float* x        = (const float*)d_in[0];
    const int*   ei       = (const int*)d_in[1];   // int32 (JAX default x64-disabled)
    const float* w_pre1   = (const float*)d_in[2];
    const float* b_pre1   = (const float*)d_in[3];
    const float* w_pre2   = (const float*)d_in[4];
    const float* b_pre2   = (const float*)d_in[5];
    const float* w_gcn0   = (const float*)d_in[6];
    const float* b_gcn0   = (const float*)d_in[7];
    const float* w_gcn1   = (const float*)d_in[8];
    const float* b_gcn1   = (const float*)d_in[9];
    const float* wih0     = (const float*)d_in[10];
    const float* whh0     = (const float*)d_in[11];
    const float* bih0     = (const float*)d_in[12];
    const float* bhh0     = (const float*)d_in[13];
    const float* wih1     = (const float*)d_in[14];
    const float* whh1     = (const float*)d_in[15];
    const float* bih1     = (const float*)d_in[16];
    const float* bhh1     = (const float*)d_in[17];
    const float* prev0    = (const float*)d_in[18];
    const float* prev1    = (const float*)d_in[19];
    const float* w_post   = (const float*)d_in[20];
    const float* b_post   = (const float*)d_in[21];

    float* out  = (float*)d_out;          // [NN]
    float* emb0 = out + NN;               // [NN, H]
    float* emb1 = emb0 + (size_t)NN * H;  // [NN, H]

    float *h0, *h1, *hw, *agg, *gcn, *gi, *gh, *deg, *dinv;
    cudaGetSymbolAddress((void**)&h0, g_h0);
    cudaGetSymbolAddress((void**)&h1, g_h1);
    cudaGetSymbolAddress((void**)&hw, g_hw);
    cudaGetSymbolAddress((void**)&agg, g_agg);
    cudaGetSymbolAddress((void**)&gcn, g_gcn);
    cudaGetSymbolAddress((void**)&gi, g_gi);
    cudaGetSymbolAddress((void**)&gh, g_gh);
    cudaGetSymbolAddress((void**)&deg, g_deg);
    cudaGetSymbolAddress((void**)&dinv, g_dinv);

    const int* e_src = ei;
    const int* e_dst = ei + NE;

    dim3 g128(1, (NN + 127) / 128);
    dim3 g384(3, (NN + 127) / 128);
    const int T = 256;
    const int n4_NH = NN * H / 4;

    // pre MLP
    sgemm_k<<<g128, T>>>(x, w_pre1, b_pre1, h0, NN, H, H, 1);
    sgemm_k<<<g128, T>>>(h0, w_pre2, b_pre2, h1, NN, H, H, 1);

    // degree / normalization (shared by both layers)
    zero_k<<<(NN / 4 + T - 1) / T, T>>>(deg, NN / 4);
    deg_acc_k<<<(NE + T - 1) / T, T>>>(e_dst, deg);
    dinv_k<<<(NN + T - 1) / T, T>>>(deg, dinv);

    // ---- layer 0 ----
    sgemm_k<<<g128, T>>>(h1, w_gcn0, nullptr, hw, NN, H, H, 0);
    zero_k<<<(n4_NH + T - 1) / T, T>>>(agg, n4_NH);
    scatter_k<<<2368, T>>>(e_src, e_dst, hw, dinv, agg);
    combine_k<<<(n4_NH + T - 1) / T, T>>>(agg, hw, dinv, b_gcn0, gcn);
    sgemm_k<<<g384, T>>>(gcn, wih0, bih0, gi, NN, H3, H, 0);
    sgemm_k<<<g384, T>>>(prev0, whh0, bhh0, gh, NN, H3, H, 0);
    gru_k<<<(NN * H + T - 1) / T, T>>>(gi, gh, prev0, emb0);

    // ---- layer 1 ----
    sgemm_k<<<g128, T>>>(emb0, w_gcn1, nullptr, hw, NN, H, H, 0);
    zero_k<<<(n4_NH + T - 1) / T, T>>>(agg, n4_NH);
    scatter_k<<<2368, T>>>(e_src, e_dst, hw, dinv, agg);
    combine_k<<<(n4_NH + T - 1) / T, T>>>(agg, hw, dinv, b_gcn1, gcn);
    sgemm_k<<<g384, T>>>(gcn, wih1, bih1, gi, NN, H3, H, 0);
    sgemm_k<<<g384, T>>>(prev1, whh1, bhh1, gh, NN, H3, H, 0);
    gru_k<<<(NN * H + T - 1) / T, T>>>(gi, gh, prev1, emb1);

    // post head
    post_k<<<(NN * 32 + T - 1) / T, T>>>(emb1, w_post, b_post, out);
}

// round 8
// speedup vs baseline: 1.3582x; 1.3582x over previous
#include <cuda_runtime.h>
#include <math.h>

#define NN 50000
#define NE 800000
#define H 128
#define H3 384

// ---------------- device scratch (no allocs allowed) ----------------
__device__ float g_h0[NN * H];
__device__ float g_h1[NN * H];
__device__ float g_hw[NN * H];
__device__ float g_gcn[NN * H];
__device__ float g_gi[NN * H3];
__device__ float g_gh[NN * H3];
__device__ float g_dinv[NN];
__device__ int   g_cnt[NN];        // counts, then reused as fill cursor
__device__ int   g_rowptr[NN + 1];
__device__ int2  g_edge[NE];       // (src, norm-as-bits) sorted by dst

// ---------------- SGEMM: C[M,Ncol] = act(A[M,K] @ B[K,Ncol] + bias) ----------------
__global__ void __launch_bounds__(256, 2) sgemm_k(
    const float* __restrict__ A, const float* __restrict__ B,
    const float* __restrict__ bias, float* __restrict__ C,
    int M, int Ncol, int K, int act)
{
    __shared__ float As[8][128];
    __shared__ float Bs[8][128];
    const int tid = threadIdx.x;
    const int bx = blockIdx.x, by = blockIdx.y;
    const int row0 = by * 128;
    const int col0 = bx * 128;
    const int aRow = tid >> 1;
    const int aCol = (tid & 1) << 2;
    const int bRow = tid >> 5;
    const int bCol = (tid & 31) << 2;
    const int tr = (tid >> 4) << 3;
    const int tc = (tid & 15) << 3;
    float acc[8][8] = {};

    for (int k0 = 0; k0 < K; k0 += 8) {
        float4 av = make_float4(0.f, 0.f, 0.f, 0.f);
        int gr = row0 + aRow;
        if (gr < M)
            av = *reinterpret_cast<const float4*>(&A[(size_t)gr * K + k0 + aCol]);
        As[aCol + 0][aRow] = av.x;
        As[aCol + 1][aRow] = av.y;
        As[aCol + 2][aRow] = av.z;
        As[aCol + 3][aRow] = av.w;
        *reinterpret_cast<float4*>(&Bs[bRow][bCol]) =
            *reinterpret_cast<const float4*>(&B[(size_t)(k0 + bRow) * Ncol + col0 + bCol]);
        __syncthreads();
#pragma unroll
        for (int k = 0; k < 8; k++) {
            float ar[8], br[8];
#pragma unroll
            for (int i = 0; i < 8; i++) ar[i] = As[k][tr + i];
#pragma unroll
            for (int j = 0; j < 8; j++) br[j] = Bs[k][tc + j];
#pragma unroll
            for (int i = 0; i < 8; i++)
#pragma unroll
                for (int j = 0; j < 8; j++)
                    acc[i][j] = fmaf(ar[i], br[j], acc[i][j]);
        }
        __syncthreads();
    }

#pragma unroll
    for (int i = 0; i < 8; i++) {
        int gr = row0 + tr + i;
        if (gr >= M) break;
#pragma unroll
        for (int j0 = 0; j0 < 8; j0 += 4) {
            float4 v;
            v.x = acc[i][j0]; v.y = acc[i][j0 + 1]; v.z = acc[i][j0 + 2]; v.w = acc[i][j0 + 3];
            if (bias) {
                const float4 bv = *reinterpret_cast<const float4*>(&bias[col0 + tc + j0]);
                v.x += bv.x; v.y += bv.y; v.z += bv.z; v.w += bv.w;
            }
            if (act) {
                v.x = v.x >= 0.f ? v.x : 0.01f * v.x;
                v.y = v.y >= 0.f ? v.y : 0.01f * v.y;
                v.z = v.z >= 0.f ? v.z : 0.01f * v.z;
                v.w = v.w >= 0.f ? v.w : 0.01f * v.w;
            }
            *reinterpret_cast<float4*>(&C[(size_t)gr * Ncol + col0 + tc + j0]) = v;
        }
    }
}

// ---------------- CSR build ----------------
__global__ void zero_int_k(int* __restrict__ p, int n)
{
    int i = blockIdx.x * blockDim.x + threadIdx.x;
    if (i < n) p[i] = 0;
}

__global__ void count_k(const int* __restrict__ dst, int* __restrict__ cnt)
{
    int i = blockIdx.x * blockDim.x + threadIdx.x;
    if (i < NE) {
        int d = dst[i];
        if ((unsigned)d < NN) atomicAdd(&cnt[d], 1);
    }
}

__global__ void dinv_k(const int* __restrict__ cnt, float* __restrict__ dinv)
{
    int i = blockIdx.x * blockDim.x + threadIdx.x;
    if (i < NN) dinv[i] = rsqrtf((float)cnt[i] + 1.0f);
}

// single-block exclusive scan of cnt[NN] -> rowptr[NN+1]
#define SCAN_T 1024
#define SCAN_C 49   // 1024*49 = 50176 >= 50000
__global__ void __launch_bounds__(SCAN_T, 1) scan_k(const int* __restrict__ cnt,
                                                    int* __restrict__ rowptr)
{
    __shared__ int ssum[SCAN_T];
    int t = threadIdx.x;
    int beg = t * SCAN_C;
    int end = min(beg + SCAN_C, NN);
    int s = 0;
    for (int i = beg; i < end; i++) s += cnt[i];
    ssum[t] = s;
    __syncthreads();
    // Hillis-Steele inclusive scan
    for (int off = 1; off < SCAN_T; off <<= 1) {
        int v = (t >= off) ? ssum[t - off] : 0;
        __syncthreads();
        ssum[t] += v;
        __syncthreads();
    }
    int run = (t > 0) ? ssum[t - 1] : 0;
    for (int i = beg; i < end; i++) {
        rowptr[i] = run;
        run += cnt[i];
    }
    if (t == SCAN_T - 1) rowptr[NN] = ssum[SCAN_T - 1];
}

__global__ void copy_cursor_k(const int* __restrict__ rowptr, int* __restrict__ cur)
{
    int i = blockIdx.x * blockDim.x + threadIdx.x;
    if (i < NN) cur[i] = rowptr[i];
}

__global__ void fill_k(const int* __restrict__ src, const int* __restrict__ dst,
                       const float* __restrict__ dinv, int* __restrict__ cur,
                       int2* __restrict__ edge)
{
    int i = blockIdx.x * blockDim.x + threadIdx.x;
    if (i >= NE) return;
    int s = src[i], d = dst[i];
    if ((unsigned)s >= NN || (unsigned)d >= NN) return;
    float nrm = dinv[s] * dinv[d];
    int pos = atomicAdd(&cur[d], 1);
    edge[pos] = make_int2(s, __float_as_int(nrm));
}

// ---------------- fused aggregate + self-loop + bias + lrelu ----------------
// one warp per dst node; lane handles 4 contiguous columns (float4)
__global__ void __launch_bounds__(256) agg_k(
    const int* __restrict__ rowptr, const int2* __restrict__ edge,
    const float* __restrict__ hw, const float* __restrict__ dinv,
    const float* __restrict__ bias, float* __restrict__ out)
{
    int warp = (blockIdx.x * blockDim.x + threadIdx.x) >> 5;
    int lane = threadIdx.x & 31;
    if (warp >= NN) return;
    int beg = rowptr[warp], end = rowptr[warp + 1];
    float di = dinv[warp];
    float d2 = di * di;
    float4 self = reinterpret_cast<const float4*>(&hw[(size_t)warp * H])[lane];
    float4 acc;
    acc.x = self.x * d2; acc.y = self.y * d2; acc.z = self.z * d2; acc.w = self.w * d2;
    for (int e = beg; e < end; e++) {
        int2 ed = __ldg(&edge[e]);               // uniform across warp (broadcast)
        float nrm = __int_as_float(ed.y);
        float4 v = __ldg(&reinterpret_cast<const float4*>(&hw[(size_t)ed.x * H])[lane]);
        acc.x = fmaf(v.x, nrm, acc.x);
        acc.y = fmaf(v.y, nrm, acc.y);
        acc.z = fmaf(v.z, nrm, acc.z);
        acc.w = fmaf(v.w, nrm, acc.w);
    }
    float4 b = reinterpret_cast<const float4*>(bias)[lane];
    acc.x += b.x; acc.y += b.y; acc.z += b.z; acc.w += b.w;
    acc.x = acc.x >= 0.f ? acc.x : 0.01f * acc.x;
    acc.y = acc.y >= 0.f ? acc.y : 0.01f * acc.y;
    acc.z = acc.z >= 0.f ? acc.z : 0.01f * acc.z;
    acc.w = acc.w >= 0.f ? acc.w : 0.01f * acc.w;
    reinterpret_cast<float4*>(&out[(size_t)warp * H])[lane] = acc;
}

// ---------------- GRU + head ----------------
__device__ __forceinline__ float sigm(float x) { return 1.0f / (1.0f + expf(-x)); }

__global__ void gru_k(const float* __restrict__ gi, const float* __restrict__ gh,
                      const float* __restrict__ prev, float* __restrict__ out)
{
    int i = blockIdx.x * blockDim.x + threadIdx.x;
    if (i >= NN * H) return;
    int nrow = i / H;
    int c = i % H;
    size_t base = (size_t)nrow * H3 + c;
    float ir = gi[base], iz = gi[base + H], inn = gi[base + 2 * H];
    float hr = gh[base], hz = gh[base + H], hn = gh[base + 2 * H];
    float r = sigm(ir + hr);
    float z = sigm(iz + hz);
    float nn_ = tanhf(inn + r * hn);
    out[i] = (1.0f - z) * nn_ + z * prev[i];
}

__global__ void post_k(const float* __restrict__ h, const float* __restrict__ w,
                       const float* __restrict__ b, float* __restrict__ out)
{
    int gwarp = (blockIdx.x * blockDim.x + threadIdx.x) >> 5;
    int lane = threadIdx.x & 31;
    if (gwarp >= NN) return;
    float4 wv = reinterpret_cast<const float4*>(w)[lane];
    float4 hv = reinterpret_cast<const float4*>(&h[(size_t)gwarp * H])[lane];
    float s = hv.x * wv.x + hv.y * wv.y + hv.z * wv.z + hv.w * wv.w;
#pragma unroll
    for (int o = 16; o; o >>= 1) s += __shfl_xor_sync(0xFFFFFFFFu, s, o);
    if (lane == 0) out[gwarp] = s + b[0];
}

// ---------------- launch ----------------
extern "C" void kernel_launch(void* const* d_in, const int* in_sizes, int n_in,
                              void* d_out, int out_size)
{
    const float* x        = (const float*)d_in[0];
    const int*   ei       = (const int*)d_in[1];   // int32
    const float* w_pre1   = (const float*)d_in[2];
    const float* b_pre1   = (const float*)d_in[3];
    const float* w_pre2   = (const float*)d_in[4];
    const float* b_pre2   = (const float*)d_in[5];
    const float* w_gcn0   = (const float*)d_in[6];
    const float* b_gcn0   = (const float*)d_in[7];
    const float* w_gcn1   = (const float*)d_in[8];
    const float* b_gcn1   = (const float*)d_in[9];
    const float* wih0     = (const float*)d_in[10];
    const float* whh0     = (const float*)d_in[11];
    const float* bih0     = (const float*)d_in[12];
    const float* bhh0     = (const float*)d_in[13];
    const float* wih1     = (const float*)d_in[14];
    const float* whh1     = (const float*)d_in[15];
    const float* bih1     = (const float*)d_in[16];
    const float* bhh1     = (const float*)d_in[17];
    const float* prev0    = (const float*)d_in[18];
    const float* prev1    = (const float*)d_in[19];
    const float* w_post   = (const float*)d_in[20];
    const float* b_post   = (const float*)d_in[21];

    float* out  = (float*)d_out;          // [NN]
    float* emb0 = out + NN;               // [NN, H]
    float* emb1 = emb0 + (size_t)NN * H;  // [NN, H]

    float *h0, *h1, *hw, *gcn, *gi, *gh, *dinv;
    int *cnt, *rowptr;
    int2 *edge;
    cudaGetSymbolAddress((void**)&h0, g_h0);
    cudaGetSymbolAddress((void**)&h1, g_h1);
    cudaGetSymbolAddress((void**)&hw, g_hw);
    cudaGetSymbolAddress((void**)&gcn, g_gcn);
    cudaGetSymbolAddress((void**)&gi, g_gi);
    cudaGetSymbolAddress((void**)&gh, g_gh);
    cudaGetSymbolAddress((void**)&dinv, g_dinv);
    cudaGetSymbolAddress((void**)&cnt, g_cnt);
    cudaGetSymbolAddress((void**)&rowptr, g_rowptr);
    cudaGetSymbolAddress((void**)&edge, g_edge);

    const int* e_src = ei;
    const int* e_dst = ei + NE;

    dim3 g128(1, (NN + 127) / 128);
    dim3 g384(3, (NN + 127) / 128);
    const int T = 256;

    // pre MLP (overlappable with CSR build in launch order)
    sgemm_k<<<g128, T>>>(x, w_pre1, b_pre1, h0, NN, H, H, 1);
    sgemm_k<<<g128, T>>>(h0, w_pre2, b_pre2, h1, NN, H, H, 1);

    // CSR build (dst-sorted)
    zero_int_k<<<(NN + T - 1) / T, T>>>(cnt, NN);
    count_k<<<(NE + T - 1) / T, T>>>(e_dst, cnt);
    dinv_k<<<(NN + T - 1) / T, T>>>(cnt, dinv);
    scan_k<<<1, SCAN_T>>>(cnt, rowptr);
    copy_cursor_k<<<(NN + T - 1) / T, T>>>(rowptr, cnt);
    fill_k<<<(NE + T - 1) / T, T>>>(e_src, e_dst, dinv, cnt, edge);

    // ---- layer 0 ----
    sgemm_k<<<g128, T>>>(h1, w_gcn0, nullptr, hw, NN, H, H, 0);
    agg_k<<<(NN * 32 + T - 1) / T, T>>>(rowptr, edge, hw, dinv, b_gcn0, gcn);
    sgemm_k<<<g384, T>>>(gcn, wih0, bih0, gi, NN, H3, H, 0);
    sgemm_k<<<g384, T>>>(prev0, whh0, bhh0, gh, NN, H3, H, 0);
    gru_k<<<(NN * H + T - 1) / T, T>>>(gi, gh, prev0, emb0);

    // ---- layer 1 ----
    sgemm_k<<<g128, T>>>(emb0, w_gcn1, nullptr, hw, NN, H, H, 0);
    agg_k<<<(NN * 32 + T - 1) / T, T>>>(rowptr, edge, hw, dinv, b_gcn1, gcn);
    sgemm_k<<<g384, T>>>(gcn, wih1, bih1, gi, NN, H3, H, 0);
    sgemm_k<<<g384, T>>>(prev1, whh1, bhh1, gh, NN, H3, H, 0);
    gru_k<<<(NN * H + T - 1) / T, T>>>(gi, gh, prev1, emb1);

    // post head
    post_k<<<(NN * 32 + T - 1) / T, T>>>(emb1, w_post, b_post, out);
}

// round 9
// speedup vs baseline: 2.0296x; 1.4943x over previous
#include <cuda_runtime.h>
#include <math.h>
#include <mma.h>

using namespace nvcuda;

#define NN 50000
#define NN_PAD 50048   // 391 * 128
#define NE 800000
#define H 128
#define H3 384

// ---------------- device scratch (no allocs allowed) ----------------
__device__ float g_h0[NN_PAD * H];
__device__ float g_h1[NN_PAD * H];
__device__ float g_hw[NN_PAD * H];
__device__ float g_gcn[NN_PAD * H];
__device__ float g_gi[NN_PAD * H3];
__device__ float g_gh[NN_PAD * H3];
__device__ float g_dinv[NN];
__device__ int   g_cnt[NN];
__device__ int   g_rowptr[NN + 1];
__device__ int2  g_edge[NE];

// ---------------- tf32 tensor-core GEMM: C = A[M,128] @ B[128,Ncol] ----------------
// BM=128, BN=128, BK=32, 256 threads (8 warps, 2x4), warp tile 64x32.
#define ASTR 36
#define BSTR 132
__global__ void __launch_bounds__(256, 2) tgemm_k(
    const float* __restrict__ A, const float* __restrict__ B,
    float* __restrict__ C, int M, int Ncol)
{
    __shared__ float As[128][ASTR];   // [row][k]
    __shared__ float Bs[32][BSTR];    // [k][col]
    const int tid = threadIdx.x;
    const int row0 = blockIdx.y * 128;
    const int col0 = blockIdx.x * 128;
    const int warp = tid >> 5;
    const int wr = warp >> 2;         // 0..1
    const int wc = warp & 3;          // 0..3

    wmma::fragment<wmma::accumulator, 16, 16, 8, float> acc[4][2];
#pragma unroll
    for (int i = 0; i < 4; i++)
#pragma unroll
        for (int j = 0; j < 2; j++)
            wmma::fill_fragment(acc[i][j], 0.0f);

    for (int k0 = 0; k0 < 128; k0 += 32) {
        // load A tile 128x32 (guarded rows, tf32-convert)
#pragma unroll
        for (int t = 0; t < 4; t++) {
            int idx = tid + t * 256;
            int r = idx >> 3;
            int c = (idx & 7) << 2;
            float4 v = make_float4(0.f, 0.f, 0.f, 0.f);
            int gr = row0 + r;
            if (gr < M)
                v = *reinterpret_cast<const float4*>(&A[(size_t)gr * 128 + k0 + c]);
            As[r][c + 0] = wmma::__float_to_tf32(v.x);
            As[r][c + 1] = wmma::__float_to_tf32(v.y);
            As[r][c + 2] = wmma::__float_to_tf32(v.z);
            As[r][c + 3] = wmma::__float_to_tf32(v.w);
        }
        // load B tile 32x128
#pragma unroll
        for (int t = 0; t < 4; t++) {
            int idx = tid + t * 256;
            int r = idx >> 5;
            int c = (idx & 31) << 2;
            float4 v = *reinterpret_cast<const float4*>(&B[(size_t)(k0 + r) * Ncol + col0 + c]);
            Bs[r][c + 0] = wmma::__float_to_tf32(v.x);
            Bs[r][c + 1] = wmma::__float_to_tf32(v.y);
            Bs[r][c + 2] = wmma::__float_to_tf32(v.z);
            Bs[r][c + 3] = wmma::__float_to_tf32(v.w);
        }
        __syncthreads();
#pragma unroll
        for (int kk = 0; kk < 32; kk += 8) {
            wmma::fragment<wmma::matrix_a, 16, 16, 8, wmma::precision::tf32, wmma::row_major> af[4];
            wmma::fragment<wmma::matrix_b, 16, 16, 8, wmma::precision::tf32, wmma::row_major> bf[2];
#pragma unroll
            for (int i = 0; i < 4; i++)
                wmma::load_matrix_sync(af[i], &As[wr * 64 + i * 16][kk], ASTR);
#pragma unroll
            for (int j = 0; j < 2; j++)
                wmma::load_matrix_sync(bf[j], &Bs[kk][wc * 32 + j * 16], BSTR);
#pragma unroll
            for (int i = 0; i < 4; i++)
#pragma unroll
                for (int j = 0; j < 2; j++)
                    wmma::mma_sync(acc[i][j], af[i], bf[j], acc[i][j]);
        }
        __syncthreads();
    }

    // direct store (outputs are padded to NN_PAD rows)
#pragma unroll
    for (int i = 0; i < 4; i++)
#pragma unroll
        for (int j = 0; j < 2; j++) {
            int r = row0 + wr * 64 + i * 16;
            int c = col0 + wc * 32 + j * 16;
            wmma::store_matrix_sync(&C[(size_t)r * Ncol + c], acc[i][j], Ncol, wmma::mem_row_major);
        }
}

// in-place bias + leaky relu over [NN, 128]
__global__ void biasact_k(float* __restrict__ p, const float* __restrict__ bias)
{
    int i = blockIdx.x * blockDim.x + threadIdx.x;
    if (i >= NN * H / 4) return;
    int c4 = i & (H / 4 - 1);
    float4 v = reinterpret_cast<float4*>(p)[i];
    float4 b = reinterpret_cast<const float4*>(bias)[c4];
    v.x += b.x; v.y += b.y; v.z += b.z; v.w += b.w;
    v.x = v.x >= 0.f ? v.x : 0.01f * v.x;
    v.y = v.y >= 0.f ? v.y : 0.01f * v.y;
    v.z = v.z >= 0.f ? v.z : 0.01f * v.z;
    v.w = v.w >= 0.f ? v.w : 0.01f * v.w;
    reinterpret_cast<float4*>(p)[i] = v;
}

// ---------------- CSR build ----------------
__global__ void zero_int_k(int* __restrict__ p, int n)
{
    int i = blockIdx.x * blockDim.x + threadIdx.x;
    if (i < n) p[i] = 0;
}

__global__ void count_k(const int* __restrict__ dst, int* __restrict__ cnt)
{
    int i = blockIdx.x * blockDim.x + threadIdx.x;
    if (i < NE) {
        int d = dst[i];
        if ((unsigned)d < NN) atomicAdd(&cnt[d], 1);
    }
}

__global__ void dinv_k(const int* __restrict__ cnt, float* __restrict__ dinv)
{
    int i = blockIdx.x * blockDim.x + threadIdx.x;
    if (i < NN) dinv[i] = rsqrtf((float)cnt[i] + 1.0f);
}

#define SCAN_T 1024
#define SCAN_C 49
__global__ void __launch_bounds__(SCAN_T, 1) scan_k(const int* __restrict__ cnt,
                                                    int* __restrict__ rowptr)
{
    __shared__ int ssum[SCAN_T];
    int t = threadIdx.x;
    int beg = t * SCAN_C;
    int end = min(beg + SCAN_C, NN);
    int s = 0;
    for (int i = beg; i < end; i++) s += cnt[i];
    ssum[t] = s;
    __syncthreads();
    for (int off = 1; off < SCAN_T; off <<= 1) {
        int v = (t >= off) ? ssum[t - off] : 0;
        __syncthreads();
        ssum[t] += v;
        __syncthreads();
    }
    int run = (t > 0) ? ssum[t - 1] : 0;
    for (int i = beg; i < end; i++) {
        rowptr[i] = run;
        run += cnt[i];
    }
    if (t == SCAN_T - 1) rowptr[NN] = ssum[SCAN_T - 1];
}

__global__ void copy_cursor_k(const int* __restrict__ rowptr, int* __restrict__ cur)
{
    int i = blockIdx.x * blockDim.x + threadIdx.x;
    if (i < NN) cur[i] = rowptr[i];
}

__global__ void fill_k(const int* __restrict__ src, const int* __restrict__ dst,
                       const float* __restrict__ dinv, int* __restrict__ cur,
                       int2* __restrict__ edge)
{
    int i = blockIdx.x * blockDim.x + threadIdx.x;
    if (i >= NE) return;
    int s = src[i], d = dst[i];
    if ((unsigned)s >= NN || (unsigned)d >= NN) return;
    float nrm = dinv[s] * dinv[d];
    int pos = atomicAdd(&cur[d], 1);
    edge[pos] = make_int2(s, __float_as_int(nrm));
}

// ---------------- fused aggregate + self-loop + bias + lrelu ----------------
__global__ void __launch_bounds__(256) agg_k(
    const int* __restrict__ rowptr, const int2* __restrict__ edge,
    const float* __restrict__ hw, const float* __restrict__ dinv,
    const float* __restrict__ bias, float* __restrict__ out)
{
    int warp = (blockIdx.x * blockDim.x + threadIdx.x) >> 5;
    int lane = threadIdx.x & 31;
    if (warp >= NN) return;
    int beg = rowptr[warp], end = rowptr[warp + 1];
    float di = dinv[warp];
    float d2 = di * di;
    float4 self = reinterpret_cast<const float4*>(&hw[(size_t)warp * H])[lane];
    float4 acc;
    acc.x = self.x * d2; acc.y = self.y * d2; acc.z = self.z * d2; acc.w = self.w * d2;
    for (int e = beg; e < end; e++) {
        int2 ed = __ldg(&edge[e]);
        float nrm = __int_as_float(ed.y);
        float4 v = __ldg(&reinterpret_cast<const float4*>(&hw[(size_t)ed.x * H])[lane]);
        acc.x = fmaf(v.x, nrm, acc.x);
        acc.y = fmaf(v.y, nrm, acc.y);
        acc.z = fmaf(v.z, nrm, acc.z);
        acc.w = fmaf(v.w, nrm, acc.w);
    }
    float4 b = reinterpret_cast<const float4*>(bias)[lane];
    acc.x += b.x; acc.y += b.y; acc.z += b.z; acc.w += b.w;
    acc.x = acc.x >= 0.f ? acc.x : 0.01f * acc.x;
    acc.y = acc.y >= 0.f ? acc.y : 0.01f * acc.y;
    acc.z = acc.z >= 0.f ? acc.z : 0.01f * acc.z;
    acc.w = acc.w >= 0.f ? acc.w : 0.01f * acc.w;
    reinterpret_cast<float4*>(&out[(size_t)warp * H])[lane] = acc;
}

// ---------------- GRU (biases folded) + head ----------------
__device__ __forceinline__ float sigm(float x) { return 1.0f / (1.0f + expf(-x)); }

__global__ void gru_k(const float* __restrict__ gi, const float* __restrict__ gh,
                      const float* __restrict__ bih, const float* __restrict__ bhh,
                      const float* __restrict__ prev, float* __restrict__ out)
{
    int i = blockIdx.x * blockDim.x + threadIdx.x;
    if (i >= NN * H) return;
    int nrow = i / H;
    int c = i % H;
    size_t base = (size_t)nrow * H3 + c;
    float ir = gi[base]         + bih[c];
    float iz = gi[base + H]     + bih[c + H];
    float inn = gi[base + 2 * H] + bih[c + 2 * H];
    float hr = gh[base]         + bhh[c];
    float hz = gh[base + H]     + bhh[c + H];
    float hn = gh[base + 2 * H] + bhh[c + 2 * H];
    float r = sigm(ir + hr);
    float z = sigm(iz + hz);
    float nn_ = tanhf(inn + r * hn);
    out[i] = (1.0f - z) * nn_ + z * prev[i];
}

__global__ void post_k(const float* __restrict__ h, const float* __restrict__ w,
                       const float* __restrict__ b, float* __restrict__ out)
{
    int gwarp = (blockIdx.x * blockDim.x + threadIdx.x) >> 5;
    int lane = threadIdx.x & 31;
    if (gwarp >= NN) return;
    float4 wv = reinterpret_cast<const float4*>(w)[lane];
    float4 hv = reinterpret_cast<const float4*>(&h[(size_t)gwarp * H])[lane];
    float s = hv.x * wv.x + hv.y * wv.y + hv.z * wv.z + hv.w * wv.w;
#pragma unroll
    for (int o = 16; o; o >>= 1) s += __shfl_xor_sync(0xFFFFFFFFu, s, o);
    if (lane == 0) out[gwarp] = s + b[0];
}

// ---------------- launch ----------------
extern "C" void kernel_launch(void* const* d_in, const int* in_sizes, int n_in,
                              void* d_out, int out_size)
{
    const float* x        = (const float*)d_in[0];
    const int*   ei       = (const int*)d_in[1];
    const float* w_pre1   = (const float*)d_in[2];
    const float* b_pre1   = (const float*)d_in[3];
    const float* w_pre2   = (const float*)d_in[4];
    const float* b_pre2   = (const float*)d_in[5];
    const float* w_gcn0   = (const float*)d_in[6];
    const float* b_gcn0   = (const float*)d_in[7];
    const float* w_gcn1   = (const float*)d_in[8];
    const float* b_gcn1   = (const float*)d_in[9];
    const float* wih0     = (const float*)d_in[10];
    const float* whh0     = (const float*)d_in[11];
    const float* bih0     = (const float*)d_in[12];
    const float* bhh0     = (const float*)d_in[13];
    const float* wih1     = (const float*)d_in[14];
    const float* whh1     = (const float*)d_in[15];
    const float* bih1     = (const float*)d_in[16];
    const float* bhh1     = (const float*)d_in[17];
    const float* prev0    = (const float*)d_in[18];
    const float* prev1    = (const float*)d_in[19];
    const float* w_post   = (const float*)d_in[20];
    const float* b_post   = (const float*)d_in[21];

    float* out  = (float*)d_out;
    float* emb0 = out + NN;
    float* emb1 = emb0 + (size_t)NN * H;

    float *h0, *h1, *hw, *gcn, *gi, *gh, *dinv;
    int *cnt, *rowptr;
    int2 *edge;
    cudaGetSymbolAddress((void**)&h0, g_h0);
    cudaGetSymbolAddress((void**)&h1, g_h1);
    cudaGetSymbolAddress((void**)&hw, g_hw);
    cudaGetSymbolAddress((void**)&gcn, g_gcn);
    cudaGetSymbolAddress((void**)&gi, g_gi);
    cudaGetSymbolAddress((void**)&gh, g_gh);
    cudaGetSymbolAddress((void**)&dinv, g_dinv);
    cudaGetSymbolAddress((void**)&cnt, g_cnt);
    cudaGetSymbolAddress((void**)&rowptr, g_rowptr);
    cudaGetSymbolAddress((void**)&edge, g_edge);

    const int* e_src = ei;
    const int* e_dst = ei + NE;

    dim3 g128(1, NN_PAD / 128);
    dim3 g384(3, NN_PAD / 128);
    const int T = 256;

    // CSR build (independent of pre MLP)
    zero_int_k<<<(NN + T - 1) / T, T>>>(cnt, NN);
    count_k<<<(NE + T - 1) / T, T>>>(e_dst, cnt);
    dinv_k<<<(NN + T - 1) / T, T>>>(cnt, dinv);
    scan_k<<<1, SCAN_T>>>(cnt, rowptr);
    copy_cursor_k<<<(NN + T - 1) / T, T>>>(rowptr, cnt);
    fill_k<<<(NE + T - 1) / T, T>>>(e_src, e_dst, dinv, cnt, edge);

    // pre MLP
    tgemm_k<<<g128, T>>>(x, w_pre1, h0, NN, H);
    biasact_k<<<(NN * H / 4 + T - 1) / T, T>>>(h0, b_pre1);
    tgemm_k<<<g128, T>>>(h0, w_pre2, h1, NN, H);
    biasact_k<<<(NN * H / 4 + T - 1) / T, T>>>(h1, b_pre2);

    // ---- layer 0 ----
    tgemm_k<<<g128, T>>>(h1, w_gcn0, hw, NN, H);
    agg_k<<<(NN * 32 + T - 1) / T, T>>>(rowptr, edge, hw, dinv, b_gcn0, gcn);
    tgemm_k<<<g384, T>>>(gcn, wih0, gi, NN, H3);
    tgemm_k<<<g384, T>>>(prev0, whh0, gh, NN, H3);
    gru_k<<<(NN * H + T - 1) / T, T>>>(gi, gh, bih0, bhh0, prev0, emb0);

    // ---- layer 1 ----
    tgemm_k<<<g128, T>>>(emb0, w_gcn1, hw, NN, H);
    agg_k<<<(NN * 32 + T - 1) / T, T>>>(rowptr, edge, hw, dinv, b_gcn1, gcn);
    tgemm_k<<<g384, T>>>(gcn, wih1, gi, NN, H3);
    tgemm_k<<<g384, T>>>(prev1, whh1, gh, NN, H3);
    gru_k<<<(NN * H + T - 1) / T, T>>>(gi, gh, bih1, bhh1, prev1, emb1);

    // post head
    post_k<<<(NN * 32 + T - 1) / T, T>>>(emb1, w_post, b_post, out);
}